// round 6
// baseline (speedup 1.0000x reference)
#include <cuda_runtime.h>

#define IMG 256
#define NPIX (IMG*IMG)
#define V 182
#define VPAD 192
#define BATCH 64
#define BPB 8                      // hist blocks per batch
#define THREADS 512
#define PIX_PER_BLOCK (NPIX/BPB)   // 8192
#define NBLK (BATCH*BPB)           // 512
#define NCOPY 4                    // replicated shared histograms

// ---------------- compile-time radius + count tables ----------------
struct Tables {
    unsigned char r[NPIX];
    int cnt[V];
};

constexpr Tables make_tables() {
    Tables t{};
    for (int i = 0; i < IMG; ++i) {
        int di = i - 128;
        int s0 = di*di + 128*128;
        int r = 0;
        while ((r+1)*(r+1) <= s0) ++r;
        for (int j = 0; j < IMG; ++j) {
            int dj = j - 128;
            int s = di*di + dj*dj;
            while ((r+1)*(r+1) <= s) ++r;   // |delta r| <= 1 per j step
            while (r > 0 && r*r > s) --r;
            t.r[i*IMG + j] = (unsigned char)r;
            t.cnt[r] += 1;
        }
    }
    return t;
}

__device__ const Tables g_tab = make_tables();

__device__ float g_part[NBLK * VPAD];     // per hist-block partials
__device__ float g_prof[BATCH * V];       // per-batch profile
__device__ float g_bmin[BATCH], g_bmax[BATCH];
__device__ int   g_ctr = 0;               // last-block ticket (reset by last block)

// ---------------- histogram kernel ----------------
__global__ __launch_bounds__(THREADS) void k_hist(const float* __restrict__ x) {
    __shared__ float sh[NCOPY][V];

    int b     = blockIdx.x / BPB;
    int chunk = blockIdx.x % BPB;
    int wcopy = (threadIdx.x >> 5) & (NCOPY - 1);

    for (int v = threadIdx.x; v < NCOPY*V; v += THREADS) sh[0][v] = 0.f;
    __syncthreads();

    const float* __restrict__ rp = x + (size_t)b * 3 * NPIX;
    const float* __restrict__ gp = rp + NPIX;
    const float* __restrict__ bp = gp + NPIX;
    const unsigned char* __restrict__ rt = g_tab.r;
    float* __restrict__ hist = sh[wcopy];

    int base = chunk * PIX_PER_BLOCK;
    #pragma unroll
    for (int it = 0; it < PIX_PER_BLOCK/(THREADS*4); ++it) {
        int p4 = base + (it*THREADS + threadIdx.x) * 4;
        float4 rr = *(const float4*)(rp + p4);
        float4 gg = *(const float4*)(gp + p4);
        float4 bb = *(const float4*)(bp + p4);
        uchar4 rq = *(const uchar4*)(rt + p4);

        float m0 = 20.f*(0.299f*rr.x + 0.587f*gg.x + 0.114f*bb.x);
        float m1 = 20.f*(0.299f*rr.y + 0.587f*gg.y + 0.114f*bb.y);
        float m2 = 20.f*(0.299f*rr.z + 0.587f*gg.z + 0.114f*bb.z);
        float m3 = 20.f*(0.299f*rr.w + 0.587f*gg.w + 0.114f*bb.w);

        // merge equal-radius neighbors before touching shared atomics
        float v = m0; unsigned cr = rq.x;
        if (rq.y == cr) { v += m1; } else { atomicAdd(&hist[cr], v); cr = rq.y; v = m1; }
        if (rq.z == cr) { v += m2; } else { atomicAdd(&hist[cr], v); cr = rq.z; v = m2; }
        if (rq.w == cr) { v += m3; } else { atomicAdd(&hist[cr], v); cr = rq.w; v = m3; }
        atomicAdd(&hist[cr], v);
    }
    __syncthreads();

    float* dst = g_part + (size_t)blockIdx.x * VPAD;
    for (int v = threadIdx.x; v < V; v += THREADS)
        dst[v] = sh[0][v] + sh[1][v] + sh[2][v] + sh[3][v];
}

// ---------------- per-batch reduce + fused last-block normalize ----------------
__global__ __launch_bounds__(192) void k_reduce(float* __restrict__ out) {
    __shared__ float smin[6], smax[6];
    __shared__ int   s_last;
    int b = blockIdx.x;
    int v = threadIdx.x;

    float pr  =  __int_as_float(0x7f800000);   // +inf for inactive lanes
    float prx = -__int_as_float(0x7f800000);
    if (v < V) {
        const float* p = g_part + (size_t)(b * BPB) * VPAD + v;
        float s = 0.f;
        #pragma unroll
        for (int c = 0; c < BPB; ++c) s += p[c * VPAD];
        float prof = s * (1.f / (float)g_tab.cnt[v]);
        g_prof[b * V + v] = prof;
        pr = prof; prx = prof;
    }
    #pragma unroll
    for (int o = 16; o; o >>= 1) {
        pr  = fminf(pr,  __shfl_xor_sync(0xFFFFFFFFu, pr,  o));
        prx = fmaxf(prx, __shfl_xor_sync(0xFFFFFFFFu, prx, o));
    }
    if ((threadIdx.x & 31) == 0) { smin[threadIdx.x>>5] = pr; smax[threadIdx.x>>5] = prx; }
    __syncthreads();
    if (threadIdx.x == 0) {
        float mn = smin[0], mx = smax[0];
        #pragma unroll
        for (int w = 1; w < 6; ++w) { mn = fminf(mn, smin[w]); mx = fmaxf(mx, smax[w]); }
        g_bmin[b] = mn; g_bmax[b] = mx;
        __threadfence();
        int t = atomicAdd(&g_ctr, 1);
        s_last = (t == BATCH - 1);
    }
    __syncthreads();

    if (!s_last) return;

    // ---- last block: global min/max over 64 batch pairs, then normalize ----
    __shared__ float s_mn, s_mx;
    if (threadIdx.x < 32) {
        float mn = fminf(g_bmin[threadIdx.x], g_bmin[threadIdx.x + 32]);
        float mx = fmaxf(g_bmax[threadIdx.x], g_bmax[threadIdx.x + 32]);
        #pragma unroll
        for (int o = 16; o; o >>= 1) {
            mn = fminf(mn, __shfl_xor_sync(0xFFFFFFFFu, mn, o));
            mx = fmaxf(mx, __shfl_xor_sync(0xFFFFFFFFu, mx, o));
        }
        if (threadIdx.x == 0) {
            s_mn = mn; s_mx = mx;
            g_ctr = 0;                      // reset for next graph replay
        }
    }
    __syncthreads();

    float mn = s_mn;
    float scale = 1.f / (s_mx - mn);
    for (int i = threadIdx.x; i < BATCH*V; i += 192)
        out[i] = (g_prof[i] - mn) * scale;
}

extern "C" void kernel_launch(void* const* d_in, const int* in_sizes, int n_in,
                              void* d_out, int out_size) {
    const float* x = (const float*)d_in[0];
    float* out = (float*)d_out;
    (void)in_sizes; (void)n_in; (void)out_size;

    k_hist<<<NBLK, THREADS>>>(x);
    k_reduce<<<BATCH, 192>>>(out);
}